// round 1
// baseline (speedup 1.0000x reference)
#include <cuda_runtime.h>
#include <cuda_bf16.h>

#define N_PTS 100000
#define CIN   256
#define CMID  64
#define COUT  256
#define KNB   27
#define LN_EPS 1e-6f

// Intermediate buffers (device globals — no allocation allowed)
__device__ float g_h [N_PTS * CMID];   // after conv1+LN+ReLU
__device__ float g_h2[N_PTS * CMID];   // after conv2+LN+ReLU

// ---------------------------------------------------------------------------
// Kernel A: h = relu(LN(feats @ W1))        feats[N,256] W1[256,64] -> h[N,64]
// 256 threads, 32 rows/block, 8 threads/row, 8 outputs (d) per thread.
// feats tile staged in smem (padded stride 260); W1 read via __ldg (L1-hot).
// ---------------------------------------------------------------------------
__global__ void __launch_bounds__(256) kA(const float* __restrict__ feats,
                                          const float* __restrict__ W1,
                                          const float* __restrict__ g1,
                                          const float* __restrict__ b1)
{
    __shared__ float fs[32 * 260];
    const int t    = threadIdx.x;
    const int base = blockIdx.x * 32;

    // Load feats tile: 32 rows x 256 = 2048 float4, 8 per thread
#pragma unroll
    for (int i = 0; i < 8; i++) {
        int u  = t + 256 * i;          // float4 id
        int r  = u >> 6;               // 64 float4 per row
        int c4 = u & 63;
        float4 v = __ldg((const float4*)(feats + (base + r) * CIN + c4 * 4));
        *(float4*)&fs[r * 260 + c4 * 4] = v;
    }
    __syncthreads();

    const int row = t >> 3;            // 0..31
    const int j   = t & 7;
    const int d0  = j * 8;

    float acc[8];
#pragma unroll
    for (int i = 0; i < 8; i++) acc[i] = 0.f;

    const float* frow = &fs[row * 260];
#pragma unroll 4
    for (int c = 0; c < 256; c++) {
        float f = frow[c];
        float4 wa = __ldg((const float4*)(W1 + c * CMID + d0));
        float4 wb = __ldg((const float4*)(W1 + c * CMID + d0 + 4));
        acc[0] += f * wa.x; acc[1] += f * wa.y; acc[2] += f * wa.z; acc[3] += f * wa.w;
        acc[4] += f * wb.x; acc[5] += f * wb.y; acc[6] += f * wb.z; acc[7] += f * wb.w;
    }

    // LayerNorm over 64 channels: reduce across the 8 threads of this row
    float s = 0.f, q = 0.f;
#pragma unroll
    for (int i = 0; i < 8; i++) { s += acc[i]; q += acc[i] * acc[i]; }
#pragma unroll
    for (int m = 4; m >= 1; m >>= 1) {
        s += __shfl_xor_sync(0xffffffffu, s, m, 8);
        q += __shfl_xor_sync(0xffffffffu, q, m, 8);
    }
    float mu  = s * (1.f / 64.f);
    float var = q * (1.f / 64.f) - mu * mu;
    float inv = rsqrtf(var + LN_EPS);

    float out[8];
#pragma unroll
    for (int i = 0; i < 8; i++) {
        float y = (acc[i] - mu) * inv * __ldg(g1 + d0 + i) + __ldg(b1 + d0 + i);
        out[i] = fmaxf(y, 0.f);
    }
    float* dst = g_h + (base + row) * CMID + d0;
    *(float4*)(dst)     = make_float4(out[0], out[1], out[2], out[3]);
    *(float4*)(dst + 4) = make_float4(out[4], out[5], out[6], out[7]);
}

// ---------------------------------------------------------------------------
// Kernel B: h2 = relu(LN( sum_k h[idx[n,k]] @ W2[k] ))
// 256 threads, 64 rows/block. Thread: slot=t/8 (2 rows), j=t%8 (8 cols).
// Per k: stage W2[k] (16KB) + gathered h tile (padded) in smem, accumulate.
// ---------------------------------------------------------------------------
__global__ void __launch_bounds__(256) kB(const int*   __restrict__ nidx,
                                          const float* __restrict__ W2,
                                          const float* __restrict__ g2,
                                          const float* __restrict__ b2)
{
    __shared__ float hs[64 * 68];      // gathered tile, padded stride 68
    __shared__ float ws[64 * 64];      // W2[k]
    __shared__ int   is[64 * KNB];     // neighbor indices for tile

    const int t    = threadIdx.x;
    const int base = blockIdx.x * 64;

    for (int u = t; u < 64 * KNB; u += 256) {
        int r  = u / KNB;
        int k  = u - r * KNB;
        int gr = base + r;
        is[u] = (gr < N_PTS) ? __ldg(nidx + gr * KNB + k) : 0;
    }

    const int slot = t >> 3;           // 0..31
    const int j    = t & 7;
    const int d0   = j * 8;
    const int r0   = slot * 2;
    const int r1   = r0 + 1;

    float acc[16];
#pragma unroll
    for (int i = 0; i < 16; i++) acc[i] = 0.f;

    for (int k = 0; k < KNB; k++) {
        __syncthreads();               // protect smem from previous iteration

        // Stage W2[k]: 4096 floats = 1024 float4, 4 per thread
        const float* wk = W2 + k * (CMID * CMID);
#pragma unroll
        for (int i = 0; i < 4; i++) {
            int u = (t + 256 * i) * 4;
            *(float4*)&ws[u] = __ldg((const float4*)(wk + u));
        }
        // Gather 64 rows of h: 64 x 16 float4
#pragma unroll
        for (int i = 0; i < 4; i++) {
            int u   = t + 256 * i;     // float4 id 0..1023
            int r   = u >> 4;
            int c4  = u & 15;
            int src = is[r * KNB + k];
            float4 v = __ldg((const float4*)(g_h + src * CMID + c4 * 4));
            *(float4*)&hs[r * 68 + c4 * 4] = v;
        }
        __syncthreads();

#pragma unroll 2
        for (int c = 0; c < 64; c++) {
            float4 wa = *(float4*)&ws[c * 64 + d0];
            float4 wb = *(float4*)&ws[c * 64 + d0 + 4];
            float f0 = hs[r0 * 68 + c];
            float f1 = hs[r1 * 68 + c];
            acc[0]  += f0 * wa.x; acc[1]  += f0 * wa.y; acc[2]  += f0 * wa.z; acc[3]  += f0 * wa.w;
            acc[4]  += f0 * wb.x; acc[5]  += f0 * wb.y; acc[6]  += f0 * wb.z; acc[7]  += f0 * wb.w;
            acc[8]  += f1 * wa.x; acc[9]  += f1 * wa.y; acc[10] += f1 * wa.z; acc[11] += f1 * wa.w;
            acc[12] += f1 * wb.x; acc[13] += f1 * wb.y; acc[14] += f1 * wb.z; acc[15] += f1 * wb.w;
        }
    }

    // LayerNorm + ReLU per row (reduce across the 8 j-threads, width 8)
    float ln_g[8], ln_b[8];
#pragma unroll
    for (int i = 0; i < 8; i++) { ln_g[i] = __ldg(g2 + d0 + i); ln_b[i] = __ldg(b2 + d0 + i); }

#pragma unroll
    for (int rr = 0; rr < 2; rr++) {
        float* a = acc + rr * 8;
        float s = 0.f, q = 0.f;
#pragma unroll
        for (int i = 0; i < 8; i++) { s += a[i]; q += a[i] * a[i]; }
#pragma unroll
        for (int m = 4; m >= 1; m >>= 1) {
            s += __shfl_xor_sync(0xffffffffu, s, m, 8);
            q += __shfl_xor_sync(0xffffffffu, q, m, 8);
        }
        float mu  = s * (1.f / 64.f);
        float var = q * (1.f / 64.f) - mu * mu;
        float inv = rsqrtf(var + LN_EPS);

        int grow = base + r0 + rr;
        if (grow < N_PTS) {
            float out[8];
#pragma unroll
            for (int i = 0; i < 8; i++) {
                float y = (a[i] - mu) * inv * ln_g[i] + ln_b[i];
                out[i] = fmaxf(y, 0.f);
            }
            float* dst = g_h2 + grow * CMID + d0;
            *(float4*)(dst)     = make_float4(out[0], out[1], out[2], out[3]);
            *(float4*)(dst + 4) = make_float4(out[4], out[5], out[6], out[7]);
        }
    }
}

// ---------------------------------------------------------------------------
// Kernel C: out = relu(LN(h2 @ W3) + feats)    h2[N,64] W3[64,256] -> [N,256]
// 256 threads, 8 rows/block, 1 warp per row, 8 outputs per thread.
// ---------------------------------------------------------------------------
__global__ void __launch_bounds__(256) kC(const float* __restrict__ feats,
                                          const float* __restrict__ W3,
                                          const float* __restrict__ g3,
                                          const float* __restrict__ b3,
                                          float* __restrict__ out)
{
    __shared__ float h2s[8 * 64];
    const int t    = threadIdx.x;
    const int base = blockIdx.x * 8;

#pragma unroll
    for (int i = 0; i < 2; i++) {
        int u = t + 256 * i;
        h2s[u] = g_h2[base * CMID + u];
    }
    __syncthreads();

    const int row  = t >> 5;           // 0..7
    const int lane = t & 31;
    const int d0   = lane * 8;

    float acc[8];
#pragma unroll
    for (int i = 0; i < 8; i++) acc[i] = 0.f;

#pragma unroll 4
    for (int c = 0; c < 64; c++) {
        float f = h2s[row * 64 + c];
        float4 wa = __ldg((const float4*)(W3 + c * COUT + d0));
        float4 wb = __ldg((const float4*)(W3 + c * COUT + d0 + 4));
        acc[0] += f * wa.x; acc[1] += f * wa.y; acc[2] += f * wa.z; acc[3] += f * wa.w;
        acc[4] += f * wb.x; acc[5] += f * wb.y; acc[6] += f * wb.z; acc[7] += f * wb.w;
    }

    // LayerNorm over 256 channels: full-warp reduction
    float s = 0.f, q = 0.f;
#pragma unroll
    for (int i = 0; i < 8; i++) { s += acc[i]; q += acc[i] * acc[i]; }
#pragma unroll
    for (int m = 16; m >= 1; m >>= 1) {
        s += __shfl_xor_sync(0xffffffffu, s, m, 32);
        q += __shfl_xor_sync(0xffffffffu, q, m, 32);
    }
    float mu  = s * (1.f / 256.f);
    float var = q * (1.f / 256.f) - mu * mu;
    float inv = rsqrtf(var + LN_EPS);

    const int grow = base + row;
    float4 fa = __ldg((const float4*)(feats + grow * CIN + d0));
    float4 fb = __ldg((const float4*)(feats + grow * CIN + d0 + 4));
    float res[8] = {fa.x, fa.y, fa.z, fa.w, fb.x, fb.y, fb.z, fb.w};

    float o[8];
#pragma unroll
    for (int i = 0; i < 8; i++) {
        float y = (acc[i] - mu) * inv * __ldg(g3 + d0 + i) + __ldg(b3 + d0 + i) + res[i];
        o[i] = fmaxf(y, 0.f);
    }
    float* dst = out + grow * COUT + d0;
    *(float4*)(dst)     = make_float4(o[0], o[1], o[2], o[3]);
    *(float4*)(dst + 4) = make_float4(o[4], o[5], o[6], o[7]);
}

// ---------------------------------------------------------------------------
extern "C" void kernel_launch(void* const* d_in, const int* in_sizes, int n_in,
                              void* d_out, int out_size)
{
    const float* feats = (const float*)d_in[0];
    const int*   nidx  = (const int*)  d_in[1];
    const float* W1    = (const float*)d_in[2];
    const float* g1    = (const float*)d_in[3];
    const float* b1    = (const float*)d_in[4];
    const float* W2    = (const float*)d_in[5];
    const float* g2    = (const float*)d_in[6];
    const float* b2    = (const float*)d_in[7];
    const float* W3    = (const float*)d_in[8];
    const float* g3    = (const float*)d_in[9];
    const float* b3    = (const float*)d_in[10];
    float* out = (float*)d_out;

    kA<<<N_PTS / 32, 256>>>(feats, W1, g1, b1);
    kB<<<(N_PTS + 63) / 64, 256>>>(nidx, W2, g2, b2);
    kC<<<N_PTS / 8, 256>>>(feats, W3, g3, b3, out);
}

// round 2
// speedup vs baseline: 1.8624x; 1.8624x over previous
#include <cuda_runtime.h>

#define N_PTS 100000
#define N_PAD 100096            // multiple of 128
#define CIN   256
#define CMID  64
#define COUT  256
#define KNB   27
#define LN_EPS 1e-6f

// Intermediate buffers, padded so tile stores need no guards
__device__ float g_h [N_PAD * CMID];
__device__ float g_h2[N_PAD * CMID];

#define SMEM_A (128*68*4 + 64*64*4)                 // 51200 B
#define SMEM_B (128*68*4 + 64*64*4 + 128*KNB*4)     // 65024 B
#define SMEM_C (64*68*4 + 64*256*4)                 // 82944 B

// ---------------------------------------------------------------------------
// Kernel A: h = relu(LN(feats @ W1))   [N,256]x[256,64] -> [N,64]
// Tile: 128 rows x 64 cols, K chunked by 64. Thread: 4 rows (stride-32) x 8 cols.
// ---------------------------------------------------------------------------
__global__ void __launch_bounds__(256) kA(const float* __restrict__ feats,
                                          const float* __restrict__ W1,
                                          const float* __restrict__ g1,
                                          const float* __restrict__ b1)
{
    extern __shared__ float sm[];
    float* fs = sm;                 // [128][68]
    float* ws = sm + 128 * 68;      // [64][64]

    const int t    = threadIdx.x;
    const int base = blockIdx.x * 128;
    const int slot = t >> 3;        // 0..31
    const int j    = t & 7;
    const int d0   = j * 8;

    float acc[4][8];
#pragma unroll
    for (int r = 0; r < 4; r++)
#pragma unroll
        for (int i = 0; i < 8; i++) acc[r][i] = 0.f;

    for (int kc = 0; kc < 4; kc++) {
        if (kc) __syncthreads();
        // Stage W1 chunk [64x64]: 1024 float4, 4/thread
#pragma unroll
        for (int i = 0; i < 4; i++) {
            int u = t + 256 * i;
            float4 v = __ldg((const float4*)(W1 + (kc * 64 + (u >> 4)) * CMID + (u & 15) * 4));
            *(float4*)&ws[(u >> 4) * 64 + (u & 15) * 4] = v;
        }
        // Stage feats chunk [128x64]: 2048 float4, 8/thread
#pragma unroll
        for (int i = 0; i < 8; i++) {
            int u = t + 256 * i;
            int r = u >> 4, c4 = u & 15;
            int gr = base + r;
            float4 v = make_float4(0.f, 0.f, 0.f, 0.f);
            if (gr < N_PTS) v = __ldg((const float4*)(feats + gr * CIN + kc * 64 + c4 * 4));
            *(float4*)&fs[r * 68 + c4 * 4] = v;
        }
        __syncthreads();

#pragma unroll 2
        for (int c = 0; c < 64; c++) {
            float4 wa = *(float4*)&ws[c * 64 + d0];
            float4 wb = *(float4*)&ws[c * 64 + d0 + 4];
#pragma unroll
            for (int rr = 0; rr < 4; rr++) {
                float f = fs[(slot + 32 * rr) * 68 + c];
                acc[rr][0] += f * wa.x; acc[rr][1] += f * wa.y;
                acc[rr][2] += f * wa.z; acc[rr][3] += f * wa.w;
                acc[rr][4] += f * wb.x; acc[rr][5] += f * wb.y;
                acc[rr][6] += f * wb.z; acc[rr][7] += f * wb.w;
            }
        }
    }

    float ln_g[8], ln_b[8];
#pragma unroll
    for (int i = 0; i < 8; i++) { ln_g[i] = __ldg(g1 + d0 + i); ln_b[i] = __ldg(b1 + d0 + i); }

#pragma unroll
    for (int rr = 0; rr < 4; rr++) {
        float s = 0.f, q = 0.f;
#pragma unroll
        for (int i = 0; i < 8; i++) { s += acc[rr][i]; q += acc[rr][i] * acc[rr][i]; }
#pragma unroll
        for (int m = 4; m >= 1; m >>= 1) {
            s += __shfl_xor_sync(0xffffffffu, s, m, 8);
            q += __shfl_xor_sync(0xffffffffu, q, m, 8);
        }
        float mu  = s * (1.f / 64.f);
        float var = q * (1.f / 64.f) - mu * mu;
        float inv = rsqrtf(var + LN_EPS);
        float o[8];
#pragma unroll
        for (int i = 0; i < 8; i++)
            o[i] = fmaxf((acc[rr][i] - mu) * inv * ln_g[i] + ln_b[i], 0.f);
        float* dst = g_h + (base + slot + 32 * rr) * CMID + d0;   // padded, no guard
        *(float4*)(dst)     = make_float4(o[0], o[1], o[2], o[3]);
        *(float4*)(dst + 4) = make_float4(o[4], o[5], o[6], o[7]);
    }
}

// ---------------------------------------------------------------------------
// Kernel B: h2 = relu(LN( sum_k gather(h)[k] @ W2[k] ))
// Tile: 128 rows. Thread: 4 rows (stride-32) x 8 cols. W2[k] + gathered tile in smem.
// ---------------------------------------------------------------------------
__global__ void __launch_bounds__(256) kB(const int*   __restrict__ nidx,
                                          const float* __restrict__ W2,
                                          const float* __restrict__ g2,
                                          const float* __restrict__ b2)
{
    extern __shared__ float sm[];
    float* hs = sm;                       // [128][68]
    float* ws = sm + 128 * 68;            // [64][64]
    int*   is = (int*)(sm + 128 * 68 + 64 * 64);  // [128*27]

    const int t    = threadIdx.x;
    const int base = blockIdx.x * 128;
    const int slot = t >> 3;
    const int j    = t & 7;
    const int d0   = j * 8;

    // Stage indices for the tile
    const int lim = (N_PTS - base) * KNB;
    for (int u = t; u < 128 * KNB; u += 256)
        is[u] = (u < lim) ? __ldg(nidx + base * KNB + u) : 0;

    float acc[4][8];
#pragma unroll
    for (int r = 0; r < 4; r++)
#pragma unroll
        for (int i = 0; i < 8; i++) acc[r][i] = 0.f;

    for (int k = 0; k < KNB; k++) {
        __syncthreads();    // covers index staging (k=0) and prior-iter compute
        // Stage W2[k] [64x64]
        const float* wk = W2 + k * (CMID * CMID);
#pragma unroll
        for (int i = 0; i < 4; i++) {
            int u = t + 256 * i;
            *(float4*)&ws[u * 4] = __ldg((const float4*)(wk + u * 4));
        }
        // Gather 128 rows of h
#pragma unroll
        for (int i = 0; i < 8; i++) {
            int u = t + 256 * i;
            int r = u >> 4, c4 = u & 15;
            int src = is[r * KNB + k];
            *(float4*)&hs[r * 68 + c4 * 4] = __ldg((const float4*)(g_h + src * CMID + c4 * 4));
        }
        __syncthreads();

#pragma unroll 2
        for (int c = 0; c < 64; c++) {
            float4 wa = *(float4*)&ws[c * 64 + d0];
            float4 wb = *(float4*)&ws[c * 64 + d0 + 4];
#pragma unroll
            for (int rr = 0; rr < 4; rr++) {
                float f = hs[(slot + 32 * rr) * 68 + c];
                acc[rr][0] += f * wa.x; acc[rr][1] += f * wa.y;
                acc[rr][2] += f * wa.z; acc[rr][3] += f * wa.w;
                acc[rr][4] += f * wb.x; acc[rr][5] += f * wb.y;
                acc[rr][6] += f * wb.z; acc[rr][7] += f * wb.w;
            }
        }
    }

    float ln_g[8], ln_b[8];
#pragma unroll
    for (int i = 0; i < 8; i++) { ln_g[i] = __ldg(g2 + d0 + i); ln_b[i] = __ldg(b2 + d0 + i); }

#pragma unroll
    for (int rr = 0; rr < 4; rr++) {
        float s = 0.f, q = 0.f;
#pragma unroll
        for (int i = 0; i < 8; i++) { s += acc[rr][i]; q += acc[rr][i] * acc[rr][i]; }
#pragma unroll
        for (int m = 4; m >= 1; m >>= 1) {
            s += __shfl_xor_sync(0xffffffffu, s, m, 8);
            q += __shfl_xor_sync(0xffffffffu, q, m, 8);
        }
        float mu  = s * (1.f / 64.f);
        float var = q * (1.f / 64.f) - mu * mu;
        float inv = rsqrtf(var + LN_EPS);
        float o[8];
#pragma unroll
        for (int i = 0; i < 8; i++)
            o[i] = fmaxf((acc[rr][i] - mu) * inv * ln_g[i] + ln_b[i], 0.f);
        float* dst = g_h2 + (base + slot + 32 * rr) * CMID + d0;  // padded
        *(float4*)(dst)     = make_float4(o[0], o[1], o[2], o[3]);
        *(float4*)(dst + 4) = make_float4(o[4], o[5], o[6], o[7]);
    }
}

// ---------------------------------------------------------------------------
// Kernel C: out = relu(LN(h2 @ W3) + feats)   [N,64]x[64,256] -> [N,256]
// Tile: 64 rows x 256 cols, K=64. Thread: 4 rows (stride-16) x 16 cols.
// ---------------------------------------------------------------------------
__global__ void __launch_bounds__(256) kC(const float* __restrict__ feats,
                                          const float* __restrict__ W3,
                                          const float* __restrict__ g3,
                                          const float* __restrict__ b3,
                                          float* __restrict__ out)
{
    extern __shared__ float sm[];
    float* hs = sm;                 // [64][68]
    float* ws = sm + 64 * 68;       // [64][256]

    const int t    = threadIdx.x;
    const int base = blockIdx.x * 64;
    const int slot = t >> 4;        // 0..15
    const int j    = t & 15;
    const int d0   = j * 16;

    // Stage h2 tile [64x64]: 1024 float4, 4/thread (g_h2 padded -> no guard)
#pragma unroll
    for (int i = 0; i < 4; i++) {
        int u = t + 256 * i;
        int r = u >> 4, c4 = u & 15;
        *(float4*)&hs[r * 68 + c4 * 4] = *(const float4*)(g_h2 + (base + r) * CMID + c4 * 4);
    }
    // Stage W3 [64x256]: 4096 float4, 16/thread
#pragma unroll
    for (int i = 0; i < 16; i++) {
        int u = t + 256 * i;
        *(float4*)&ws[u * 4] = __ldg((const float4*)(W3 + u * 4));
    }
    __syncthreads();

    float acc[4][16];
#pragma unroll
    for (int r = 0; r < 4; r++)
#pragma unroll
        for (int i = 0; i < 16; i++) acc[r][i] = 0.f;

#pragma unroll 2
    for (int c = 0; c < 64; c++) {
        float4 w0 = *(float4*)&ws[c * 256 + d0];
        float4 w1 = *(float4*)&ws[c * 256 + d0 + 4];
        float4 w2 = *(float4*)&ws[c * 256 + d0 + 8];
        float4 w3 = *(float4*)&ws[c * 256 + d0 + 12];
#pragma unroll
        for (int rr = 0; rr < 4; rr++) {
            float f = hs[(slot + 16 * rr) * 68 + c];
            acc[rr][0]  += f * w0.x; acc[rr][1]  += f * w0.y; acc[rr][2]  += f * w0.z; acc[rr][3]  += f * w0.w;
            acc[rr][4]  += f * w1.x; acc[rr][5]  += f * w1.y; acc[rr][6]  += f * w1.z; acc[rr][7]  += f * w1.w;
            acc[rr][8]  += f * w2.x; acc[rr][9]  += f * w2.y; acc[rr][10] += f * w2.z; acc[rr][11] += f * w2.w;
            acc[rr][12] += f * w3.x; acc[rr][13] += f * w3.y; acc[rr][14] += f * w3.z; acc[rr][15] += f * w3.w;
        }
    }

    float ln_g[16], ln_b[16];
#pragma unroll
    for (int i = 0; i < 16; i++) { ln_g[i] = __ldg(g3 + d0 + i); ln_b[i] = __ldg(b3 + d0 + i); }

#pragma unroll
    for (int rr = 0; rr < 4; rr++) {
        const int grow = base + slot + 16 * rr;
        float s = 0.f, q = 0.f;
#pragma unroll
        for (int i = 0; i < 16; i++) { s += acc[rr][i]; q += acc[rr][i] * acc[rr][i]; }
#pragma unroll
        for (int m = 8; m >= 1; m >>= 1) {
            s += __shfl_xor_sync(0xffffffffu, s, m, 16);
            q += __shfl_xor_sync(0xffffffffu, q, m, 16);
        }
        float mu  = s * (1.f / 256.f);
        float var = q * (1.f / 256.f) - mu * mu;
        float inv = rsqrtf(var + LN_EPS);

        if (grow < N_PTS) {
            float4 fa = __ldg((const float4*)(feats + grow * CIN + d0));
            float4 fb = __ldg((const float4*)(feats + grow * CIN + d0 + 4));
            float4 fc = __ldg((const float4*)(feats + grow * CIN + d0 + 8));
            float4 fd = __ldg((const float4*)(feats + grow * CIN + d0 + 12));
            float res[16] = {fa.x, fa.y, fa.z, fa.w, fb.x, fb.y, fb.z, fb.w,
                             fc.x, fc.y, fc.z, fc.w, fd.x, fd.y, fd.z, fd.w};
            float o[16];
#pragma unroll
            for (int i = 0; i < 16; i++)
                o[i] = fmaxf((acc[rr][i] - mu) * inv * ln_g[i] + ln_b[i] + res[i], 0.f);
            float* dst = out + grow * COUT + d0;
            *(float4*)(dst)      = make_float4(o[0],  o[1],  o[2],  o[3]);
            *(float4*)(dst + 4)  = make_float4(o[4],  o[5],  o[6],  o[7]);
            *(float4*)(dst + 8)  = make_float4(o[8],  o[9],  o[10], o[11]);
            *(float4*)(dst + 12) = make_float4(o[12], o[13], o[14], o[15]);
        }
    }
}

// ---------------------------------------------------------------------------
extern "C" void kernel_launch(void* const* d_in, const int* in_sizes, int n_in,
                              void* d_out, int out_size)
{
    const float* feats = (const float*)d_in[0];
    const int*   nidx  = (const int*)  d_in[1];
    const float* W1    = (const float*)d_in[2];
    const float* g1    = (const float*)d_in[3];
    const float* b1    = (const float*)d_in[4];
    const float* W2    = (const float*)d_in[5];
    const float* g2    = (const float*)d_in[6];
    const float* b2    = (const float*)d_in[7];
    const float* W3    = (const float*)d_in[8];
    const float* g3    = (const float*)d_in[9];
    const float* b3    = (const float*)d_in[10];
    float* out = (float*)d_out;

    cudaFuncSetAttribute(kA, cudaFuncAttributeMaxDynamicSharedMemorySize, SMEM_A);
    cudaFuncSetAttribute(kB, cudaFuncAttributeMaxDynamicSharedMemorySize, SMEM_B);
    cudaFuncSetAttribute(kC, cudaFuncAttributeMaxDynamicSharedMemorySize, SMEM_C);

    kA<<<(N_PTS + 127) / 128, 256, SMEM_A>>>(feats, W1, g1, b1);
    kB<<<(N_PTS + 127) / 128, 256, SMEM_B>>>(nidx, W2, g2, b2);
    kC<<<(N_PTS + 63) / 64, 256, SMEM_C>>>(feats, W3, g3, b3, out);
}

// round 3
// speedup vs baseline: 1.8907x; 1.0152x over previous
#include <cuda_runtime.h>

#define N_PTS 100000
#define N_PAD 100096            // multiple of 128
#define CIN   256
#define CMID  64
#define COUT  256
#define KNB   27
#define LN_EPS 1e-6f

typedef unsigned long long u64;

__device__ float g_h [N_PAD * CMID];
__device__ float g_h2[N_PAD * CMID];

#define SMEM_A ((128*65 + 64*64) * 4)               // 49856 B
#define SMEM_B ((128*65 + 64*64 + 128*KNB) * 4)     // 63680 B
#define SMEM_C ((64*65 + 64*256) * 4)               // 82176 B

// packed fp32x2 helpers (FFMA2 — only reachable via PTX)
__device__ __forceinline__ u64 pack2(float f) {
    u64 r; unsigned u = __float_as_uint(f);
    asm("mov.b64 %0, {%1, %1};" : "=l"(r) : "r"(u));
    return r;
}
__device__ __forceinline__ void ffma2(u64& d, u64 a, u64 b) {
    asm("fma.rn.f32x2 %0, %1, %2, %0;" : "+l"(d) : "l"(a), "l"(b));
}
__device__ __forceinline__ float2 unpack2(u64 v) {
    float lo, hi;
    asm("mov.b64 {%0, %1}, %2;" : "=f"(lo), "=f"(hi) : "l"(v));
    return make_float2(lo, hi);
}

// ---------------------------------------------------------------------------
// Kernel A: h = relu(LN(feats @ W1))   [N,256]x[256,64] -> [N,64]
// Tile 128 rows x 64 cols, K chunked by 64.
// Warp w: rows (w>>1)*32 + lane, cols (w&1)*32..+32 (16 f32x2 accumulators).
// ---------------------------------------------------------------------------
__global__ void __launch_bounds__(256, 2) kA(const float* __restrict__ feats,
                                             const float* __restrict__ W1,
                                             const float* __restrict__ g1,
                                             const float* __restrict__ b1)
{
    extern __shared__ float sm[];
    float* fs = sm;                 // [128][65]
    float* ws = sm + 128 * 65;      // [64][64]

    const int t    = threadIdx.x;
    const int base = blockIdx.x * 128;
    const int lane = t & 31;
    const int w    = t >> 5;
    const int rg   = w >> 1, ch = w & 1;
    const int row  = rg * 32 + lane;
    const float* wcol = ws + ch * 32;

    u64 acc[16];
#pragma unroll
    for (int i = 0; i < 16; i++) acc[i] = 0ULL;

    for (int kc = 0; kc < 4; kc++) {
        if (kc) __syncthreads();
        // Stage W1 chunk [64x64] (rows kc*64..): contiguous, float4 copy
        const float* wsrc = W1 + kc * 64 * CMID;
#pragma unroll
        for (int i = 0; i < 4; i++) {
            int u = t + 256 * i;
            *(float4*)&ws[u * 4] = __ldg((const float4*)(wsrc + u * 4));
        }
        // Stage feats chunk [128x64] -> stride-65 scalar stores
#pragma unroll
        for (int i = 0; i < 8; i++) {
            int u = t + 256 * i;
            int r = u >> 4, c4 = u & 15;
            int gr = base + r;
            float4 v = make_float4(0.f, 0.f, 0.f, 0.f);
            if (gr < N_PTS) v = __ldg((const float4*)(feats + gr * CIN + kc * 64 + c4 * 4));
            float* p = &fs[r * 65 + c4 * 4];
            p[0] = v.x; p[1] = v.y; p[2] = v.z; p[3] = v.w;
        }
        __syncthreads();

#pragma unroll 4
        for (int c = 0; c < 64; c++) {
            u64 ff = pack2(fs[row * 65 + c]);
            const ulonglong2* wp = (const ulonglong2*)(wcol + c * 64);
#pragma unroll
            for (int j = 0; j < 8; j++) {
                ulonglong2 wv = wp[j];
                ffma2(acc[2 * j],     wv.x, ff);
                ffma2(acc[2 * j + 1], wv.y, ff);
            }
        }
    }

    // LN over 64 cols: combine the 2 ch-halves via smem
    __syncthreads();
    float2* red = (float2*)ws;      // [128][2]
    float s = 0.f, q = 0.f;
#pragma unroll
    for (int i = 0; i < 16; i++) {
        float2 v = unpack2(acc[i]);
        s += v.x + v.y; q += v.x * v.x + v.y * v.y;
    }
    red[row * 2 + ch] = make_float2(s, q);
    __syncthreads();
    float2 pa = red[row * 2], pb = red[row * 2 + 1];
    float mu  = (pa.x + pb.x) * (1.f / 64.f);
    float var = (pa.y + pb.y) * (1.f / 64.f) - mu * mu;
    float inv = rsqrtf(var + LN_EPS);

    float* dst = g_h + (base + row) * CMID + ch * 32;   // padded, no guard
#pragma unroll
    for (int j = 0; j < 8; j++) {
        float2 v = unpack2(acc[2 * (j >> 1) + (j & 1)]); // keep order: acc pairs are cols 4j..
        (void)v;
    }
#pragma unroll
    for (int j = 0; j < 8; j++) {
        float2 v0 = unpack2(acc[2 * j]);
        float2 v1 = unpack2(acc[2 * j + 1]);
        int c0 = ch * 32 + j * 4;
        float4 o;
        o.x = fmaxf((v0.x - mu) * inv * __ldg(g1 + c0)     + __ldg(b1 + c0),     0.f);
        o.y = fmaxf((v0.y - mu) * inv * __ldg(g1 + c0 + 1) + __ldg(b1 + c0 + 1), 0.f);
        o.z = fmaxf((v1.x - mu) * inv * __ldg(g1 + c0 + 2) + __ldg(b1 + c0 + 2), 0.f);
        o.w = fmaxf((v1.y - mu) * inv * __ldg(g1 + c0 + 3) + __ldg(b1 + c0 + 3), 0.f);
        *(float4*)(dst + j * 4) = o;
    }
}

// ---------------------------------------------------------------------------
// Kernel B: h2 = relu(LN( sum_k gather(h)[k] @ W2[k] ))
// Tile 128 rows. Same warp layout as kA.
// ---------------------------------------------------------------------------
__global__ void __launch_bounds__(256, 2) kB(const int*   __restrict__ nidx,
                                             const float* __restrict__ W2,
                                             const float* __restrict__ g2,
                                             const float* __restrict__ b2)
{
    extern __shared__ float sm[];
    float* hs = sm;                       // [128][65]
    float* ws = sm + 128 * 65;            // [64][64]
    int*   is = (int*)(sm + 128 * 65 + 64 * 64);   // [128*27]

    const int t    = threadIdx.x;
    const int base = blockIdx.x * 128;
    const int lane = t & 31;
    const int w    = t >> 5;
    const int rg   = w >> 1, ch = w & 1;
    const int row  = rg * 32 + lane;
    const float* wcol = ws + ch * 32;

    const int lim = (N_PTS - base) * KNB;
    for (int u = t; u < 128 * KNB; u += 256)
        is[u] = (u < lim) ? __ldg(nidx + base * KNB + u) : 0;

    u64 acc[16];
#pragma unroll
    for (int i = 0; i < 16; i++) acc[i] = 0ULL;

    for (int k = 0; k < KNB; k++) {
        __syncthreads();
        const float* wk = W2 + k * (CMID * CMID);
#pragma unroll
        for (int i = 0; i < 4; i++) {
            int u = t + 256 * i;
            *(float4*)&ws[u * 4] = __ldg((const float4*)(wk + u * 4));
        }
#pragma unroll
        for (int i = 0; i < 8; i++) {
            int u = t + 256 * i;
            int r = u >> 4, c4 = u & 15;
            int src = is[r * KNB + k];
            float4 v = __ldg((const float4*)(g_h + src * CMID + c4 * 4));
            float* p = &hs[r * 65 + c4 * 4];
            p[0] = v.x; p[1] = v.y; p[2] = v.z; p[3] = v.w;
        }
        __syncthreads();

#pragma unroll 4
        for (int c = 0; c < 64; c++) {
            u64 ff = pack2(hs[row * 65 + c]);
            const ulonglong2* wp = (const ulonglong2*)(wcol + c * 64);
#pragma unroll
            for (int j = 0; j < 8; j++) {
                ulonglong2 wv = wp[j];
                ffma2(acc[2 * j],     wv.x, ff);
                ffma2(acc[2 * j + 1], wv.y, ff);
            }
        }
    }

    __syncthreads();
    float2* red = (float2*)ws;
    float s = 0.f, q = 0.f;
#pragma unroll
    for (int i = 0; i < 16; i++) {
        float2 v = unpack2(acc[i]);
        s += v.x + v.y; q += v.x * v.x + v.y * v.y;
    }
    red[row * 2 + ch] = make_float2(s, q);
    __syncthreads();
    float2 pa = red[row * 2], pb = red[row * 2 + 1];
    float mu  = (pa.x + pb.x) * (1.f / 64.f);
    float var = (pa.y + pb.y) * (1.f / 64.f) - mu * mu;
    float inv = rsqrtf(var + LN_EPS);

    float* dst = g_h2 + (base + row) * CMID + ch * 32;
#pragma unroll
    for (int j = 0; j < 8; j++) {
        float2 v0 = unpack2(acc[2 * j]);
        float2 v1 = unpack2(acc[2 * j + 1]);
        int c0 = ch * 32 + j * 4;
        float4 o;
        o.x = fmaxf((v0.x - mu) * inv * __ldg(g2 + c0)     + __ldg(b2 + c0),     0.f);
        o.y = fmaxf((v0.y - mu) * inv * __ldg(g2 + c0 + 1) + __ldg(b2 + c0 + 1), 0.f);
        o.z = fmaxf((v1.x - mu) * inv * __ldg(g2 + c0 + 2) + __ldg(b2 + c0 + 2), 0.f);
        o.w = fmaxf((v1.y - mu) * inv * __ldg(g2 + c0 + 3) + __ldg(b2 + c0 + 3), 0.f);
        *(float4*)(dst + j * 4) = o;
    }
}

// ---------------------------------------------------------------------------
// Kernel C: out = relu(LN(h2 @ W3) + feats)   [N,64]x[64,256] -> [N,256]
// Tile 64 rows x 256 cols, 512 threads.
// Warp w (0..15): rows (w>>3)*32 + lane, cols (w&7)*32..+32.
// ---------------------------------------------------------------------------
__global__ void __launch_bounds__(512, 1) kC(const float* __restrict__ feats,
                                             const float* __restrict__ W3,
                                             const float* __restrict__ g3,
                                             const float* __restrict__ b3,
                                             float* __restrict__ out)
{
    extern __shared__ float sm[];
    float* hs = sm;                 // [64][65]
    float* ws = sm + 64 * 65;       // [64][256]

    const int t    = threadIdx.x;
    const int base = blockIdx.x * 64;
    const int lane = t & 31;
    const int w    = t >> 5;
    const int rg   = w >> 3, cb = w & 7;
    const int row  = rg * 32 + lane;
    const float* wcol = ws + cb * 32;

    // Stage h2 tile [64x64] -> stride-65 scalars (g_h2 padded, no guard)
#pragma unroll
    for (int i = 0; i < 2; i++) {
        int u = t + 512 * i;
        int r = u >> 4, c4 = u & 15;
        float4 v = *(const float4*)(g_h2 + (base + r) * CMID + c4 * 4);
        float* p = &hs[r * 65 + c4 * 4];
        p[0] = v.x; p[1] = v.y; p[2] = v.z; p[3] = v.w;
    }
    // Stage W3 [64x256]
#pragma unroll
    for (int i = 0; i < 8; i++) {
        int u = t + 512 * i;
        *(float4*)&ws[u * 4] = __ldg((const float4*)(W3 + u * 4));
    }
    __syncthreads();

    u64 acc[16];
#pragma unroll
    for (int i = 0; i < 16; i++) acc[i] = 0ULL;

#pragma unroll 4
    for (int c = 0; c < 64; c++) {
        u64 ff = pack2(hs[row * 65 + c]);
        const ulonglong2* wp = (const ulonglong2*)(wcol + c * 256);
#pragma unroll
        for (int j = 0; j < 8; j++) {
            ulonglong2 wv = wp[j];
            ffma2(acc[2 * j],     wv.x, ff);
            ffma2(acc[2 * j + 1], wv.y, ff);
        }
    }

    // LN over 256 cols: combine the 8 cb-slices via smem
    __syncthreads();
    float2* red = (float2*)hs;      // [64][8]
    float s = 0.f, q = 0.f;
#pragma unroll
    for (int i = 0; i < 16; i++) {
        float2 v = unpack2(acc[i]);
        s += v.x + v.y; q += v.x * v.x + v.y * v.y;
    }
    red[row * 8 + cb] = make_float2(s, q);
    __syncthreads();
    float S = 0.f, Q = 0.f;
#pragma unroll
    for (int i = 0; i < 8; i++) {
        float2 p = red[row * 8 + i];
        S += p.x; Q += p.y;
    }
    float mu  = S * (1.f / 256.f);
    float var = Q * (1.f / 256.f) - mu * mu;
    float inv = rsqrtf(var + LN_EPS);

    const int grow = base + row;
    if (grow < N_PTS) {
        float* dst = out + grow * COUT + cb * 32;
        const float* fsrc = feats + grow * CIN + cb * 32;
#pragma unroll
        for (int j = 0; j < 8; j++) {
            float2 v0 = unpack2(acc[2 * j]);
            float2 v1 = unpack2(acc[2 * j + 1]);
            int c0 = cb * 32 + j * 4;
            float4 r4 = __ldg((const float4*)(fsrc + j * 4));
            float4 o;
            o.x = fmaxf((v0.x - mu) * inv * __ldg(g3 + c0)     + __ldg(b3 + c0)     + r4.x, 0.f);
            o.y = fmaxf((v0.y - mu) * inv * __ldg(g3 + c0 + 1) + __ldg(b3 + c0 + 1) + r4.y, 0.f);
            o.z = fmaxf((v1.x - mu) * inv * __ldg(g3 + c0 + 2) + __ldg(b3 + c0 + 2) + r4.z, 0.f);
            o.w = fmaxf((v1.y - mu) * inv * __ldg(g3 + c0 + 3) + __ldg(b3 + c0 + 3) + r4.w, 0.f);
            *(float4*)(dst + j * 4) = o;
        }
    }
}

// ---------------------------------------------------------------------------
extern "C" void kernel_launch(void* const* d_in, const int* in_sizes, int n_in,
                              void* d_out, int out_size)
{
    const float* feats = (const float*)d_in[0];
    const int*   nidx  = (const int*)  d_in[1];
    const float* W1    = (const float*)d_in[2];
    const float* g1    = (const float*)d_in[3];
    const float* b1    = (const float*)d_in[4];
    const float* W2    = (const float*)d_in[5];
    const float* g2    = (const float*)d_in[6];
    const float* b2    = (const float*)d_in[7];
    const float* W3    = (const float*)d_in[8];
    const float* g3    = (const float*)d_in[9];
    const float* b3    = (const float*)d_in[10];
    float* out = (float*)d_out;

    cudaFuncSetAttribute(kA, cudaFuncAttributeMaxDynamicSharedMemorySize, SMEM_A);
    cudaFuncSetAttribute(kB, cudaFuncAttributeMaxDynamicSharedMemorySize, SMEM_B);
    cudaFuncSetAttribute(kC, cudaFuncAttributeMaxDynamicSharedMemorySize, SMEM_C);

    kA<<<(N_PTS + 127) / 128, 256, SMEM_A>>>(feats, W1, g1, b1);
    kB<<<(N_PTS + 127) / 128, 256, SMEM_B>>>(nidx, W2, g2, b2);
    kC<<<(N_PTS + 63) / 64, 512, SMEM_C>>>(feats, W3, g3, b3, out);
}

// round 4
// speedup vs baseline: 2.7024x; 1.4293x over previous
#include <cuda_runtime.h>

#define N_PTS 100000
#define N_PAD 100096            // multiple of 256
#define CIN   256
#define CMID  64
#define COUT  256
#define KNB   27
#define LN_EPS 1e-6f

typedef unsigned long long u64;

__device__ float g_h [N_PAD * CMID];
__device__ float g_h2[N_PAD * CMID];

#define SMEM_AB ((256*65 + 64*64) * 4)   // 82944 B
#define SMEM_C  ((64*65 + 64*256) * 4)   // 82176 B

// packed fp32x2 helpers (FFMA2 — only reachable via PTX)
__device__ __forceinline__ u64 pack2(float f) {
    u64 r; unsigned u = __float_as_uint(f);
    asm("mov.b64 %0, {%1, %1};" : "=l"(r) : "r"(u));
    return r;
}
__device__ __forceinline__ void ffma2(u64& d, u64 a, u64 b) {
    asm("fma.rn.f32x2 %0, %1, %2, %0;" : "+l"(d) : "l"(a), "l"(b));
}
__device__ __forceinline__ float2 unpack2(u64 v) {
    float lo, hi;
    asm("mov.b64 {%0, %1}, %2;" : "=f"(lo), "=f"(hi) : "l"(v));
    return make_float2(lo, hi);
}

// ---------------------------------------------------------------------------
// Kernel A: h = relu(LN(feats @ W1))   tile 256 rows x 64 cols, K chunks of 64
// 256 thr = 8 warps: wr=w>>1 (4), wc=w&1 (2). lane: tr=lane>>2, tc=lane&3.
// Thread: 8 rows (tr*4+rr, +32) x 8 cols (tc*8). acc[8][4] f32x2.
// ---------------------------------------------------------------------------
__global__ void __launch_bounds__(256, 2) kA(const float* __restrict__ feats,
                                             const float* __restrict__ W1,
                                             const float* __restrict__ g1,
                                             const float* __restrict__ b1)
{
    extern __shared__ float sm[];
    float* fs = sm;                 // [256][65]
    float* ws = sm + 256 * 65;      // [64][64]

    const int t    = threadIdx.x;
    const int base = blockIdx.x * 256;
    const int lane = t & 31, w = t >> 5;
    const int wr = w >> 1, wc = w & 1;
    const int tr = lane >> 2, tc = lane & 3;
    const int rbase = wr * 64 + tr * 4;      // + (i&3) + 32*(i>>2)
    const int d0    = wc * 32 + tc * 8;

    u64 acc[8][4];
#pragma unroll
    for (int i = 0; i < 8; i++)
#pragma unroll
        for (int p = 0; p < 4; p++) acc[i][p] = 0ULL;

    for (int kc = 0; kc < 4; kc++) {
        if (kc) __syncthreads();
        const float* wsrc = W1 + kc * 64 * CMID;
#pragma unroll
        for (int i = 0; i < 4; i++) {
            int u = t + 256 * i;
            *(float4*)&ws[u * 4] = __ldg((const float4*)(wsrc + u * 4));
        }
#pragma unroll
        for (int i = 0; i < 16; i++) {
            int u = t + 256 * i;
            int r = u >> 4, c4 = u & 15;
            int gr = base + r;
            float4 v = make_float4(0.f, 0.f, 0.f, 0.f);
            if (gr < N_PTS) v = __ldg((const float4*)(feats + gr * CIN + kc * 64 + c4 * 4));
            float* p = &fs[r * 65 + c4 * 4];
            p[0] = v.x; p[1] = v.y; p[2] = v.z; p[3] = v.w;
        }
        __syncthreads();

#pragma unroll 2
        for (int c = 0; c < 64; c++) {
            u64 A2[8];
#pragma unroll
            for (int i = 0; i < 8; i++)
                A2[i] = pack2(fs[(rbase + (i & 3) + 32 * (i >> 2)) * 65 + c]);
            ulonglong2 w0 = *(const ulonglong2*)&ws[c * 64 + d0];
            ulonglong2 w1 = *(const ulonglong2*)&ws[c * 64 + d0 + 4];
#pragma unroll
            for (int i = 0; i < 8; i++) {
                ffma2(acc[i][0], w0.x, A2[i]);
                ffma2(acc[i][1], w0.y, A2[i]);
                ffma2(acc[i][2], w1.x, A2[i]);
                ffma2(acc[i][3], w1.y, A2[i]);
            }
        }
    }

    // Epilogue: LN over 64 cols (2 col-warps), partials via shfl(width4)+smem
    __syncthreads();
    float2* red = (float2*)ws;      // [256][2]
#pragma unroll
    for (int i = 0; i < 8; i++) {
        float s = 0.f, q = 0.f;
#pragma unroll
        for (int p = 0; p < 4; p++) {
            float2 v = unpack2(acc[i][p]);
            s += v.x + v.y; q += v.x * v.x + v.y * v.y;
        }
        s += __shfl_xor_sync(0xffffffffu, s, 1, 4);
        q += __shfl_xor_sync(0xffffffffu, q, 1, 4);
        s += __shfl_xor_sync(0xffffffffu, s, 2, 4);
        q += __shfl_xor_sync(0xffffffffu, q, 2, 4);
        if (tc == 0) red[(rbase + (i & 3) + 32 * (i >> 2)) * 2 + wc] = make_float2(s, q);
    }
    __syncthreads();

    float4 ga = __ldg((const float4*)(g1 + d0)), gb = __ldg((const float4*)(g1 + d0 + 4));
    float4 ba = __ldg((const float4*)(b1 + d0)), bb = __ldg((const float4*)(b1 + d0 + 4));
    float lg[8] = {ga.x, ga.y, ga.z, ga.w, gb.x, gb.y, gb.z, gb.w};
    float lb[8] = {ba.x, ba.y, ba.z, ba.w, bb.x, bb.y, bb.z, bb.w};

#pragma unroll
    for (int i = 0; i < 8; i++) {
        int row = rbase + (i & 3) + 32 * (i >> 2);
        float2 pa = red[row * 2], pb = red[row * 2 + 1];
        float mu  = (pa.x + pb.x) * (1.f / 64.f);
        float var = (pa.y + pb.y) * (1.f / 64.f) - mu * mu;
        float inv = rsqrtf(var + LN_EPS);
        float o[8];
#pragma unroll
        for (int p = 0; p < 4; p++) {
            float2 v = unpack2(acc[i][p]);
            o[2 * p]     = fmaxf((v.x - mu) * inv * lg[2 * p]     + lb[2 * p],     0.f);
            o[2 * p + 1] = fmaxf((v.y - mu) * inv * lg[2 * p + 1] + lb[2 * p + 1], 0.f);
        }
        float* dst = g_h + (base + row) * CMID + d0;   // padded, no guard
        *(float4*)(dst)     = make_float4(o[0], o[1], o[2], o[3]);
        *(float4*)(dst + 4) = make_float4(o[4], o[5], o[6], o[7]);
    }
}

// ---------------------------------------------------------------------------
// Kernel B: h2 = relu(LN( sum_k gather(h)[k] @ W2[k] ))   tile 256 x 64
// Same layout as kA; indices read from global (L1-resident per tile).
// ---------------------------------------------------------------------------
__global__ void __launch_bounds__(256, 2) kB(const int*   __restrict__ nidx,
                                             const float* __restrict__ W2,
                                             const float* __restrict__ g2,
                                             const float* __restrict__ b2)
{
    extern __shared__ float sm[];
    float* hs = sm;                 // [256][65]
    float* ws = sm + 256 * 65;      // [64][64]

    const int t    = threadIdx.x;
    const int base = blockIdx.x * 256;
    const int lane = t & 31, w = t >> 5;
    const int wr = w >> 1, wc = w & 1;
    const int tr = lane >> 2, tc = lane & 3;
    const int rbase = wr * 64 + tr * 4;
    const int d0    = wc * 32 + tc * 8;

    u64 acc[8][4];
#pragma unroll
    for (int i = 0; i < 8; i++)
#pragma unroll
        for (int p = 0; p < 4; p++) acc[i][p] = 0ULL;

    for (int k = 0; k < KNB; k++) {
        __syncthreads();
        const float* wk = W2 + k * (CMID * CMID);
#pragma unroll
        for (int i = 0; i < 4; i++) {
            int u = t + 256 * i;
            *(float4*)&ws[u * 4] = __ldg((const float4*)(wk + u * 4));
        }
#pragma unroll
        for (int i = 0; i < 16; i++) {
            int u = t + 256 * i;
            int r = u >> 4, c4 = u & 15;
            int gr = base + r;
            int src = (gr < N_PTS) ? __ldg(nidx + gr * KNB + k) : 0;
            float4 v = __ldg((const float4*)(g_h + src * CMID + c4 * 4));
            float* p = &hs[r * 65 + c4 * 4];
            p[0] = v.x; p[1] = v.y; p[2] = v.z; p[3] = v.w;
        }
        __syncthreads();

#pragma unroll 2
        for (int c = 0; c < 64; c++) {
            u64 A2[8];
#pragma unroll
            for (int i = 0; i < 8; i++)
                A2[i] = pack2(hs[(rbase + (i & 3) + 32 * (i >> 2)) * 65 + c]);
            ulonglong2 w0 = *(const ulonglong2*)&ws[c * 64 + d0];
            ulonglong2 w1 = *(const ulonglong2*)&ws[c * 64 + d0 + 4];
#pragma unroll
            for (int i = 0; i < 8; i++) {
                ffma2(acc[i][0], w0.x, A2[i]);
                ffma2(acc[i][1], w0.y, A2[i]);
                ffma2(acc[i][2], w1.x, A2[i]);
                ffma2(acc[i][3], w1.y, A2[i]);
            }
        }
    }

    __syncthreads();
    float2* red = (float2*)ws;
#pragma unroll
    for (int i = 0; i < 8; i++) {
        float s = 0.f, q = 0.f;
#pragma unroll
        for (int p = 0; p < 4; p++) {
            float2 v = unpack2(acc[i][p]);
            s += v.x + v.y; q += v.x * v.x + v.y * v.y;
        }
        s += __shfl_xor_sync(0xffffffffu, s, 1, 4);
        q += __shfl_xor_sync(0xffffffffu, q, 1, 4);
        s += __shfl_xor_sync(0xffffffffu, s, 2, 4);
        q += __shfl_xor_sync(0xffffffffu, q, 2, 4);
        if (tc == 0) red[(rbase + (i & 3) + 32 * (i >> 2)) * 2 + wc] = make_float2(s, q);
    }
    __syncthreads();

    float4 ga = __ldg((const float4*)(g2 + d0)), gb = __ldg((const float4*)(g2 + d0 + 4));
    float4 ba = __ldg((const float4*)(b2 + d0)), bb = __ldg((const float4*)(b2 + d0 + 4));
    float lg[8] = {ga.x, ga.y, ga.z, ga.w, gb.x, gb.y, gb.z, gb.w};
    float lb[8] = {ba.x, ba.y, ba.z, ba.w, bb.x, bb.y, bb.z, bb.w};

#pragma unroll
    for (int i = 0; i < 8; i++) {
        int row = rbase + (i & 3) + 32 * (i >> 2);
        float2 pa = red[row * 2], pb = red[row * 2 + 1];
        float mu  = (pa.x + pb.x) * (1.f / 64.f);
        float var = (pa.y + pb.y) * (1.f / 64.f) - mu * mu;
        float inv = rsqrtf(var + LN_EPS);
        float o[8];
#pragma unroll
        for (int p = 0; p < 4; p++) {
            float2 v = unpack2(acc[i][p]);
            o[2 * p]     = fmaxf((v.x - mu) * inv * lg[2 * p]     + lb[2 * p],     0.f);
            o[2 * p + 1] = fmaxf((v.y - mu) * inv * lg[2 * p + 1] + lb[2 * p + 1], 0.f);
        }
        float* dst = g_h2 + (base + row) * CMID + d0;  // padded
        *(float4*)(dst)     = make_float4(o[0], o[1], o[2], o[3]);
        *(float4*)(dst + 4) = make_float4(o[4], o[5], o[6], o[7]);
    }
}

// ---------------------------------------------------------------------------
// Kernel C: out = relu(LN(h2 @ W3) + feats)   tile 64 rows x 256 cols, K=64
// 256 thr = 8 col-warps. Thread: 8 rows (tr*4+rr, +32) x 8 cols.
// ---------------------------------------------------------------------------
__global__ void __launch_bounds__(256, 2) kC(const float* __restrict__ feats,
                                             const float* __restrict__ W3,
                                             const float* __restrict__ g3,
                                             const float* __restrict__ b3,
                                             float* __restrict__ out)
{
    extern __shared__ float sm[];
    float* hs = sm;                 // [64][65]
    float* ws = sm + 64 * 65;       // [64][256]

    const int t    = threadIdx.x;
    const int base = blockIdx.x * 64;
    const int lane = t & 31, w = t >> 5;     // w = col-warp 0..7
    const int tr = lane >> 2, tc = lane & 3;
    const int rbase = tr * 4;
    const int d0    = w * 32 + tc * 8;

    // Stage h2 tile [64][64] (padded source, no guard)
#pragma unroll
    for (int i = 0; i < 4; i++) {
        int u = t + 256 * i;
        int r = u >> 4, c4 = u & 15;
        float4 v = *(const float4*)(g_h2 + (base + r) * CMID + c4 * 4);
        float* p = &hs[r * 65 + c4 * 4];
        p[0] = v.x; p[1] = v.y; p[2] = v.z; p[3] = v.w;
    }
    // Stage W3 [64][256]
#pragma unroll
    for (int i = 0; i < 16; i++) {
        int u = t + 256 * i;
        *(float4*)&ws[u * 4] = __ldg((const float4*)(W3 + u * 4));
    }
    __syncthreads();

    u64 acc[8][4];
#pragma unroll
    for (int i = 0; i < 8; i++)
#pragma unroll
        for (int p = 0; p < 4; p++) acc[i][p] = 0ULL;

#pragma unroll 2
    for (int c = 0; c < 64; c++) {
        u64 A2[8];
#pragma unroll
        for (int i = 0; i < 8; i++)
            A2[i] = pack2(hs[(rbase + (i & 3) + 32 * (i >> 2)) * 65 + c]);
        ulonglong2 w0 = *(const ulonglong2*)&ws[c * 256 + d0];
        ulonglong2 w1 = *(const ulonglong2*)&ws[c * 256 + d0 + 4];
#pragma unroll
        for (int i = 0; i < 8; i++) {
            ffma2(acc[i][0], w0.x, A2[i]);
            ffma2(acc[i][1], w0.y, A2[i]);
            ffma2(acc[i][2], w1.x, A2[i]);
            ffma2(acc[i][3], w1.y, A2[i]);
        }
    }

    // LN over 256 cols (8 col-warps)
    __syncthreads();
    float2* red = (float2*)hs;      // [64][8]
#pragma unroll
    for (int i = 0; i < 8; i++) {
        float s = 0.f, q = 0.f;
#pragma unroll
        for (int p = 0; p < 4; p++) {
            float2 v = unpack2(acc[i][p]);
            s += v.x + v.y; q += v.x * v.x + v.y * v.y;
        }
        s += __shfl_xor_sync(0xffffffffu, s, 1, 4);
        q += __shfl_xor_sync(0xffffffffu, q, 1, 4);
        s += __shfl_xor_sync(0xffffffffu, s, 2, 4);
        q += __shfl_xor_sync(0xffffffffu, q, 2, 4);
        if (tc == 0) red[(rbase + (i & 3) + 32 * (i >> 2)) * 8 + w] = make_float2(s, q);
    }
    __syncthreads();

    float4 ga = __ldg((const float4*)(g3 + d0)), gb = __ldg((const float4*)(g3 + d0 + 4));
    float4 ba = __ldg((const float4*)(b3 + d0)), bb = __ldg((const float4*)(b3 + d0 + 4));
    float lg[8] = {ga.x, ga.y, ga.z, ga.w, gb.x, gb.y, gb.z, gb.w};
    float lb[8] = {ba.x, ba.y, ba.z, ba.w, bb.x, bb.y, bb.z, bb.w};

#pragma unroll
    for (int i = 0; i < 8; i++) {
        int row  = rbase + (i & 3) + 32 * (i >> 2);
        int grow = base + row;
        float S = 0.f, Q = 0.f;
#pragma unroll
        for (int cw = 0; cw < 8; cw++) {
            float2 p = red[row * 8 + cw];
            S += p.x; Q += p.y;
        }
        float mu  = S * (1.f / 256.f);
        float var = Q * (1.f / 256.f) - mu * mu;
        float inv = rsqrtf(var + LN_EPS);

        if (grow < N_PTS) {
            float4 fa = __ldg((const float4*)(feats + grow * CIN + d0));
            float4 fb = __ldg((const float4*)(feats + grow * CIN + d0 + 4));
            float res[8] = {fa.x, fa.y, fa.z, fa.w, fb.x, fb.y, fb.z, fb.w};
            float o[8];
#pragma unroll
            for (int p = 0; p < 4; p++) {
                float2 v = unpack2(acc[i][p]);
                o[2 * p]     = fmaxf((v.x - mu) * inv * lg[2 * p]     + lb[2 * p]     + res[2 * p],     0.f);
                o[2 * p + 1] = fmaxf((v.y - mu) * inv * lg[2 * p + 1] + lb[2 * p + 1] + res[2 * p + 1], 0.f);
            }
            float* dst = out + grow * COUT + d0;
            *(float4*)(dst)     = make_float4(o[0], o[1], o[2], o[3]);
            *(float4*)(dst + 4) = make_float4(o[4], o[5], o[6], o[7]);
        }
    }
}

// ---------------------------------------------------------------------------
extern "C" void kernel_launch(void* const* d_in, const int* in_sizes, int n_in,
                              void* d_out, int out_size)
{
    const float* feats = (const float*)d_in[0];
    const int*   nidx  = (const int*)  d_in[1];
    const float* W1    = (const float*)d_in[2];
    const float* g1    = (const float*)d_in[3];
    const float* b1    = (const float*)d_in[4];
    const float* W2    = (const float*)d_in[5];
    const float* g2    = (const float*)d_in[6];
    const float* b2    = (const float*)d_in[7];
    const float* W3    = (const float*)d_in[8];
    const float* g3    = (const float*)d_in[9];
    const float* b3    = (const float*)d_in[10];
    float* out = (float*)d_out;

    cudaFuncSetAttribute(kA, cudaFuncAttributeMaxDynamicSharedMemorySize, SMEM_AB);
    cudaFuncSetAttribute(kB, cudaFuncAttributeMaxDynamicSharedMemorySize, SMEM_AB);
    cudaFuncSetAttribute(kC, cudaFuncAttributeMaxDynamicSharedMemorySize, SMEM_C);

    kA<<<N_PAD / 256, 256, SMEM_AB>>>(feats, W1, g1, b1);
    kB<<<N_PAD / 256, 256, SMEM_AB>>>(nidx, W2, g2, b2);
    kC<<<(N_PTS + 63) / 64, 256, SMEM_C>>>(feats, W3, g3, b3, out);
}